// round 6
// baseline (speedup 1.0000x reference)
#include <cuda_runtime.h>

// Problem: inputs [8,128,128,64] f32, beta [64,16] f32
// out[e, c] = inputs[e] * u[e%64, c],  u = beta^2 / rowsum(beta^2)
// out flat: n4 = 2^25 float4s. (i = (g>>2)&63, j = g&3) has period 256 in g;
// grid stride is a multiple of 256 -> per-thread u is loop-invariant.

#define D_DIM 64
#define BLOCKS 2048
#define THREADS 256
#define STRIDE (BLOCKS * THREADS)      // 2^19 float4s per grid step
#define ITERS 64                       // 2^25 / STRIDE  (fixed: was wrongly 16)
#define BATCH 16                       // front-loaded loads per pass
#define PASSES (ITERS / BATCH)         // 4

__global__ void __launch_bounds__(THREADS) fused_broadcast_mul(
    const float* __restrict__ in, const float* __restrict__ beta,
    float4* __restrict__ out) {
    unsigned int g = blockIdx.x * THREADS + threadIdx.x;
    unsigned int i = (g >> 2) & (D_DIM - 1);  // beta row
    unsigned int j = g & 3u;                  // which float4 quarter of the row

    // ---- one-time prologue: this thread's u quarter, in registers ----
    const float4* br = reinterpret_cast<const float4*>(beta) + i * 4;
    float4 q0 = __ldg(br + 0);
    float4 q1 = __ldg(br + 1);
    float4 q2 = __ldg(br + 2);
    float4 q3 = __ldg(br + 3);
    float s = q0.x * q0.x + q0.y * q0.y + q0.z * q0.z + q0.w * q0.w
            + q1.x * q1.x + q1.y * q1.y + q1.z * q1.z + q1.w * q1.w
            + q2.x * q2.x + q2.y * q2.y + q2.z * q2.z + q2.w * q2.w
            + q3.x * q3.x + q3.y * q3.y + q3.z * q3.z + q3.w * q3.w;
    float inv = 1.0f / s;
    float4 bq = (j == 0) ? q0 : (j == 1) ? q1 : (j == 2) ? q2 : q3;
    const float4 u = make_float4(bq.x * bq.x * inv, bq.y * bq.y * inv,
                                 bq.z * bq.z * inv, bq.w * bq.w * inv);

    // ---- 4 passes: 16 independent loads, then 16 FMUL+STG.128 ----
    const float* ip = in + (g >> 2);
    float4* op = out + g;

#pragma unroll
    for (int p = 0; p < PASSES; ++p) {
        float x[BATCH];
#pragma unroll
        for (int k = 0; k < BATCH; ++k)
            x[k] = __ldg(ip + k * (STRIDE / 4));   // input fits L2 -> mostly L2 hits

#pragma unroll
        for (int k = 0; k < BATCH; ++k) {
            float4 r = make_float4(x[k] * u.x, x[k] * u.y,
                                   x[k] * u.z, x[k] * u.w);
            __stcs(op + k * STRIDE, r);            // evict-first write stream
        }
        ip += (STRIDE / 4) * BATCH;
        op += STRIDE * BATCH;
    }
}

extern "C" void kernel_launch(void* const* d_in, const int* in_sizes, int n_in,
                              void* d_out, int out_size) {
    const float* inputs = (const float*)d_in[0];  // 8*128*128*64 = 8388608
    const float* beta   = (const float*)d_in[1];  // 64*16 = 1024
    float4* out = (float4*)d_out;

    fused_broadcast_mul<<<BLOCKS, THREADS>>>(inputs, beta, out);
}

// round 7
// speedup vs baseline: 1.1643x; 1.1643x over previous
#include <cuda_runtime.h>

// Problem: inputs [8,128,128,64] f32, beta [64,16] f32
// out[e, c] = inputs[e] * u[e%64, c],  u = beta^2 / rowsum(beta^2)
// out flat: n4 = 2^25 float4s.
//
// Block-contiguous layout: block b owns float4s [b*32768, (b+1)*32768) — a
// contiguous 512 KiB output region. Threads advance by 256 float4/iteration,
// so g mod 256 == tid is invariant -> per-thread u quarter lives in registers,
// and all batched load/store offsets are small compile-time immediates.

#define D_DIM 64
#define BLOCKS 1024
#define THREADS 256
#define CHUNK 32768                  // float4s per block (2^25 / 1024)
#define BATCH 8
#define PASSES 16                    // CHUNK / (THREADS * BATCH)

__global__ void __launch_bounds__(THREADS, 8) fused_broadcast_mul(
    const float* __restrict__ in, const float* __restrict__ beta,
    float4* __restrict__ out) {
    const unsigned int tid = threadIdx.x;
    const unsigned int i = tid >> 2;          // beta row (0..63)
    const unsigned int j = tid & 3u;          // which float4 quarter of the row

    // ---- one-time prologue: this thread's u quarter, in registers ----
    const float4* br = reinterpret_cast<const float4*>(beta) + i * 4;
    float4 q0 = __ldg(br + 0);
    float4 q1 = __ldg(br + 1);
    float4 q2 = __ldg(br + 2);
    float4 q3 = __ldg(br + 3);
    float s = q0.x * q0.x + q0.y * q0.y + q0.z * q0.z + q0.w * q0.w
            + q1.x * q1.x + q1.y * q1.y + q1.z * q1.z + q1.w * q1.w
            + q2.x * q2.x + q2.y * q2.y + q2.z * q2.z + q2.w * q2.w
            + q3.x * q3.x + q3.y * q3.y + q3.z * q3.z + q3.w * q3.w;
    float inv = 1.0f / s;
    float4 bq = (j == 0) ? q0 : (j == 1) ? q1 : (j == 2) ? q2 : q3;
    const float4 u = make_float4(bq.x * bq.x * inv, bq.y * bq.y * inv,
                                 bq.z * bq.z * inv, bq.w * bq.w * inv);

    // ---- contiguous chunk streaming: 8 immediate-offset loads, 8 stores ----
    unsigned int g0 = blockIdx.x * CHUNK + tid;     // this thread's first float4
    const float* ip = in + (g0 >> 2);               // advances 64 floats/iter
    float4* op = out + g0;                          // advances 256 float4/iter

#pragma unroll
    for (int p = 0; p < PASSES; ++p) {
        float x[BATCH];
#pragma unroll
        for (int k = 0; k < BATCH; ++k)
            x[k] = __ldg(ip + k * (THREADS / 4));   // +256B immediates
#pragma unroll
        for (int k = 0; k < BATCH; ++k) {
            float4 r = make_float4(x[k] * u.x, x[k] * u.y,
                                   x[k] * u.z, x[k] * u.w);
            __stcs(op + k * THREADS, r);            // +4KiB immediates, evict-first
        }
        ip += (THREADS / 4) * BATCH;
        op += THREADS * BATCH;
    }
}

extern "C" void kernel_launch(void* const* d_in, const int* in_sizes, int n_in,
                              void* d_out, int out_size) {
    const float* inputs = (const float*)d_in[0];  // 8*128*128*64 = 8388608
    const float* beta   = (const float*)d_in[1];  // 64*16 = 1024
    float4* out = (float4*)d_out;

    fused_broadcast_mul<<<BLOCKS, THREADS>>>(inputs, beta, out);
}